// round 2
// baseline (speedup 1.0000x reference)
#include <cuda_runtime.h>
#include <cuda_bf16.h>

#define N_NODES 50000
#define N_EDGES 800000
#define IN_NF 64
#define HID 128
#define OUT_NF 64
#define EH 64   // EDGE_HID

// ---------------- scratch (no allocs allowed) ----------------
__device__ float g_h[N_NODES * HID];     // node features between layers
__device__ float g_agg[N_NODES * EH];    // per-layer message aggregation
__device__ int   g_mask_u8;              // 1 if masks are uint8, 0 if int32

__device__ __forceinline__ float silu(float x) {
    return x / (1.0f + __expf(-x));
}

// ---------------- mask dtype detection (deterministic) ----------------
// If the bool masks were exported as uint8, interpreting the first
// 50000 bytes as int32 words yields values > 1 almost surely (random 0/1
// bytes packed 4 per word). If exported as int32, every word is 0 or 1.
__global__ void detect_mask_kernel(const unsigned int* __restrict__ m) {
    int bad = 0;
    for (int i = threadIdx.x; i < N_NODES / 4; i += blockDim.x) {
        if (m[i] > 1u) bad = 1;
    }
    bad = __syncthreads_or(bad);
    if (threadIdx.x == 0) g_mask_u8 = bad;
}

// ---------------- zero the aggregation buffer ----------------
__global__ void zero_agg_kernel() {
    int i = blockIdx.x * blockDim.x + threadIdx.x;   // exactly 800000 float4
    reinterpret_cast<float4*>(g_agg)[i] = make_float4(0.f, 0.f, 0.f, 0.f);
}

// ---------------- input embedding: g_h = h_in @ Wi + bi ----------------
// [50000,64] @ [64,128]; 16 rows per block, 128 threads (thread = out col)
__global__ void embed_in_kernel(const float* __restrict__ h_in,
                                const float* __restrict__ W,
                                const float* __restrict__ b) {
    __shared__ float Ws[64 * 128];
    __shared__ float xs[16][64];
    int tid = threadIdx.x;
    for (int i = tid; i < 64 * 128; i += 128) Ws[i] = W[i];
    int r0 = blockIdx.x * 16;
    for (int i = tid; i < 16 * 64; i += 128) {
        int rr = i >> 6, k = i & 63;
        xs[rr][k] = h_in[(r0 + rr) * 64 + k];
    }
    __syncthreads();
    int c = tid;
    float bc = b[c];
    for (int rr = 0; rr < 16; rr++) {
        float acc = bc;
#pragma unroll 8
        for (int k = 0; k < 64; k++) acc = fmaf(xs[rr][k], Ws[k * 128 + c], acc);
        g_h[(r0 + rr) * 128 + c] = acc;
    }
}

// ---------------- output embedding: out = g_h @ Wo + bo ----------------
// [50000,128] @ [128,64]; 16 rows per block, 256 threads
__global__ void embed_out_kernel(const float* __restrict__ W,
                                 const float* __restrict__ b,
                                 float* __restrict__ out) {
    __shared__ float Ws[128 * 64];
    __shared__ float xs[16][128];
    int tid = threadIdx.x;
    for (int i = tid; i < 128 * 64; i += 256) Ws[i] = W[i];
    int r0 = blockIdx.x * 16;
    for (int i = tid; i < 16 * 128; i += 256) {
        int rr = i >> 7, k = i & 127;
        xs[rr][k] = g_h[(r0 + rr) * 128 + k];
    }
    __syncthreads();
    int c = tid & 63;
    int q = tid >> 6;   // 0..3
    float bc = b[c];
    for (int rr = q; rr < 16; rr += 4) {
        float acc = bc;
#pragma unroll 8
        for (int k = 0; k < 128; k++) acc = fmaf(xs[rr][k], Ws[k * 64 + c], acc);
        out[(r0 + rr) * 64 + c] = acc;
    }
}

// ---------------- edge kernel ----------------
// Per warp: tile of 8 edges. feat = [h[row] || h[col]] (256), two-layer
// SiLU MLP (256->64->64), scaled atomic scatter-add into g_agg[row].
// Lane layout: er = lane>>3 owns edges {er, er+4}; cg = lane&7 owns cols
// {4cg..4cg+3} and {32+4cg..+3} (conflict-free float4 LDS of W rows).
#define FEAT_STRIDE 260   // 260 % 32 == 4 -> er groups hit distinct banks
#define M_STRIDE 68

__global__ void __launch_bounds__(256)
edge_kernel(const int* __restrict__ edges,
            const float* __restrict__ W1, const float* __restrict__ b1,
            const float* __restrict__ W2, const float* __restrict__ b2,
            float C, int nE) {
    extern __shared__ float sm[];
    float* W1s = sm;                  // 256*64 = 16384
    float* W2s = W1s + 16384;         // 64*64  = 4096
    float* b1s = W2s + 4096;          // 64
    float* b2s = b1s + 64;            // 64
    float* featAll = b2s + 64;        // 8 warps * 8 edges * 260
    float* mAll = featAll + 8 * 8 * FEAT_STRIDE;  // 8 * 8 * 68
    __shared__ int idxS[8][16];

    int tid = threadIdx.x;
    for (int i = tid; i < 16384; i += 256) W1s[i] = W1[i];
    for (int i = tid; i < 4096; i += 256) W2s[i] = W2[i];
    if (tid < 64) { b1s[tid] = b1[tid]; b2s[tid] = b2[tid]; }
    __syncthreads();

    int wid = tid >> 5, lane = tid & 31;
    float* featS = featAll + wid * (8 * FEAT_STRIDE);
    float* mS = mAll + wid * (8 * M_STRIDE);
    int* idx = idxS[wid];
    const int* rows = edges;
    const int* cols = edges + nE;

    int er = lane >> 3;       // 0..3
    int cg = lane & 7;        // 0..7
    int er4 = er + 4;
    const float4* W1v = reinterpret_cast<const float4*>(W1s);
    const float4* W2v = reinterpret_cast<const float4*>(W2s);
    float4 b1A = make_float4(b1s[4*cg], b1s[4*cg+1], b1s[4*cg+2], b1s[4*cg+3]);
    float4 b1B = make_float4(b1s[32+4*cg], b1s[32+4*cg+1], b1s[32+4*cg+2], b1s[32+4*cg+3]);
    float4 b2A = make_float4(b2s[4*cg], b2s[4*cg+1], b2s[4*cg+2], b2s[4*cg+3]);
    float4 b2B = make_float4(b2s[32+4*cg], b2s[32+4*cg+1], b2s[32+4*cg+2], b2s[32+4*cg+3]);

    int gw = blockIdx.x * 8 + wid;
    int nwarp = gridDim.x * 8;
    int ngroups = (nE + 7) >> 3;

    for (int g = gw; g < ngroups; g += nwarp) {
        int e0 = g * 8;
        if (lane < 8) {
            int e = e0 + lane;
            int ee = (e < nE) ? e : 0;
            idx[lane] = rows[ee];
            idx[lane + 8] = cols[ee];
        }
        __syncwarp();
        // gather [8 edges][256] = h[row] (0..127) || h[col] (128..255)
        for (int i = lane; i < 2048; i += 32) {
            int e = i >> 8, k = i & 255;
            int node = (k < 128) ? idx[e] : idx[e + 8];
            featS[e * FEAT_STRIDE + k] = g_h[node * 128 + (k & 127)];
        }
        __syncwarp();

        // ---- layer 1: 256 -> 64 ----
        float4 aA0 = b1A, aB0 = b1B, aA1 = b1A, aB1 = b1B;
        const float* fp0 = featS + er * FEAT_STRIDE;
        const float* fp1 = featS + er4 * FEAT_STRIDE;
#pragma unroll 4
        for (int k = 0; k < 256; k++) {
            float f0 = fp0[k], f1 = fp1[k];
            float4 wA = W1v[k * 16 + cg];
            float4 wB = W1v[k * 16 + 8 + cg];
            aA0.x = fmaf(f0, wA.x, aA0.x); aA0.y = fmaf(f0, wA.y, aA0.y);
            aA0.z = fmaf(f0, wA.z, aA0.z); aA0.w = fmaf(f0, wA.w, aA0.w);
            aB0.x = fmaf(f0, wB.x, aB0.x); aB0.y = fmaf(f0, wB.y, aB0.y);
            aB0.z = fmaf(f0, wB.z, aB0.z); aB0.w = fmaf(f0, wB.w, aB0.w);
            aA1.x = fmaf(f1, wA.x, aA1.x); aA1.y = fmaf(f1, wA.y, aA1.y);
            aA1.z = fmaf(f1, wA.z, aA1.z); aA1.w = fmaf(f1, wA.w, aA1.w);
            aB1.x = fmaf(f1, wB.x, aB1.x); aB1.y = fmaf(f1, wB.y, aB1.y);
            aB1.z = fmaf(f1, wB.z, aB1.z); aB1.w = fmaf(f1, wB.w, aB1.w);
        }
        float* m0 = mS + er * M_STRIDE;
        float* m1 = mS + er4 * M_STRIDE;
        m0[4*cg]   = silu(aA0.x); m0[4*cg+1] = silu(aA0.y);
        m0[4*cg+2] = silu(aA0.z); m0[4*cg+3] = silu(aA0.w);
        m0[32+4*cg]   = silu(aB0.x); m0[32+4*cg+1] = silu(aB0.y);
        m0[32+4*cg+2] = silu(aB0.z); m0[32+4*cg+3] = silu(aB0.w);
        m1[4*cg]   = silu(aA1.x); m1[4*cg+1] = silu(aA1.y);
        m1[4*cg+2] = silu(aA1.z); m1[4*cg+3] = silu(aA1.w);
        m1[32+4*cg]   = silu(aB1.x); m1[32+4*cg+1] = silu(aB1.y);
        m1[32+4*cg+2] = silu(aB1.z); m1[32+4*cg+3] = silu(aB1.w);
        __syncwarp();

        // ---- layer 2: 64 -> 64 ----
        float4 cA0 = b2A, cB0 = b2B, cA1 = b2A, cB1 = b2B;
#pragma unroll 4
        for (int k = 0; k < 64; k++) {
            float f0 = m0[k], f1 = m1[k];
            float4 wA = W2v[k * 16 + cg];
            float4 wB = W2v[k * 16 + 8 + cg];
            cA0.x = fmaf(f0, wA.x, cA0.x); cA0.y = fmaf(f0, wA.y, cA0.y);
            cA0.z = fmaf(f0, wA.z, cA0.z); cA0.w = fmaf(f0, wA.w, cA0.w);
            cB0.x = fmaf(f0, wB.x, cB0.x); cB0.y = fmaf(f0, wB.y, cB0.y);
            cB0.z = fmaf(f0, wB.z, cB0.z); cB0.w = fmaf(f0, wB.w, cB0.w);
            cA1.x = fmaf(f1, wA.x, cA1.x); cA1.y = fmaf(f1, wA.y, cA1.y);
            cA1.z = fmaf(f1, wA.z, cA1.z); cA1.w = fmaf(f1, wA.w, cA1.w);
            cB1.x = fmaf(f1, wB.x, cB1.x); cB1.y = fmaf(f1, wB.y, cB1.y);
            cB1.z = fmaf(f1, wB.z, cB1.z); cB1.w = fmaf(f1, wB.w, cB1.w);
        }

        int rA = idx[er], rB = idx[er4];
        bool vA = (e0 + er) < nE;
        bool vB = (e0 + er4) < nE;
        if (vA) {
            float* a = g_agg + rA * 64;
            atomicAdd(a + 4*cg,     silu(cA0.x) * C);
            atomicAdd(a + 4*cg + 1, silu(cA0.y) * C);
            atomicAdd(a + 4*cg + 2, silu(cA0.z) * C);
            atomicAdd(a + 4*cg + 3, silu(cA0.w) * C);
            atomicAdd(a + 32 + 4*cg,     silu(cB0.x) * C);
            atomicAdd(a + 32 + 4*cg + 1, silu(cB0.y) * C);
            atomicAdd(a + 32 + 4*cg + 2, silu(cB0.z) * C);
            atomicAdd(a + 32 + 4*cg + 3, silu(cB0.w) * C);
        }
        if (vB) {
            float* a = g_agg + rB * 64;
            atomicAdd(a + 4*cg,     silu(cA1.x) * C);
            atomicAdd(a + 4*cg + 1, silu(cA1.y) * C);
            atomicAdd(a + 4*cg + 2, silu(cA1.z) * C);
            atomicAdd(a + 4*cg + 3, silu(cA1.w) * C);
            atomicAdd(a + 32 + 4*cg,     silu(cB1.x) * C);
            atomicAdd(a + 32 + 4*cg + 1, silu(cB1.y) * C);
            atomicAdd(a + 32 + 4*cg + 2, silu(cB1.z) * C);
            atomicAdd(a + 32 + 4*cg + 3, silu(cB1.w) * C);
        }
        __syncwarp();
    }
}
#define EDGE_SMEM_FLOATS (16384 + 4096 + 64 + 64 + 8*8*FEAT_STRIDE + 8*8*M_STRIDE)
#define EDGE_SMEM_BYTES (EDGE_SMEM_FLOATS * 4)

// ---------------- node kernel ----------------
// upd = silu([h || agg] @ W1 + b1) @ W2 + b2; h = mask ? h + upd : h
// Warp per row; lane owns cols {lane, lane+32, lane+64, lane+96}.
__global__ void __launch_bounds__(256)
node_kernel(const void* __restrict__ mask,
            const float* __restrict__ W1, const float* __restrict__ b1,
            const float* __restrict__ W2, const float* __restrict__ b2) {
    extern __shared__ float sm[];
    float* W1s = sm;                   // 192*128 = 24576
    float* W2s = W1s + 24576;          // 128*128 = 16384
    float* b1s = W2s + 16384;          // 128
    float* b2s = b1s + 128;            // 128
    float* xAll = b2s + 128;           // 8 * 196
    float* mAll = xAll + 8 * 196;      // 8 * 132

    int tid = threadIdx.x;
    for (int i = tid; i < 24576; i += 256) W1s[i] = W1[i];
    for (int i = tid; i < 16384; i += 256) W2s[i] = W2[i];
    if (tid < 128) { b1s[tid] = b1[tid]; b2s[tid] = b2[tid]; }
    __syncthreads();

    int wid = tid >> 5, lane = tid & 31;
    float* xS = xAll + wid * 196;
    float* mS = mAll + wid * 132;
    int mu8 = g_mask_u8;

    int gw = blockIdx.x * 8 + wid;
    int nw = gridDim.x * 8;
    for (int r = gw; r < N_NODES; r += nw) {
        for (int i = lane; i < 192; i += 32)
            xS[i] = (i < 128) ? g_h[r * 128 + i] : g_agg[r * 64 + (i - 128)];
        __syncwarp();

        float a0 = b1s[lane], a1 = b1s[lane + 32],
              a2 = b1s[lane + 64], a3 = b1s[lane + 96];
#pragma unroll 4
        for (int k = 0; k < 192; k++) {
            float f = xS[k];
            a0 = fmaf(f, W1s[k * 128 + lane],       a0);
            a1 = fmaf(f, W1s[k * 128 + lane + 32],  a1);
            a2 = fmaf(f, W1s[k * 128 + lane + 64],  a2);
            a3 = fmaf(f, W1s[k * 128 + lane + 96],  a3);
        }
        mS[lane]      = silu(a0);
        mS[lane + 32] = silu(a1);
        mS[lane + 64] = silu(a2);
        mS[lane + 96] = silu(a3);
        __syncwarp();

        float c0 = b2s[lane], c1 = b2s[lane + 32],
              c2 = b2s[lane + 64], c3 = b2s[lane + 96];
#pragma unroll 4
        for (int k = 0; k < 128; k++) {
            float f = mS[k];
            c0 = fmaf(f, W2s[k * 128 + lane],       c0);
            c1 = fmaf(f, W2s[k * 128 + lane + 32],  c1);
            c2 = fmaf(f, W2s[k * 128 + lane + 64],  c2);
            c3 = fmaf(f, W2s[k * 128 + lane + 96],  c3);
        }
        bool mv = mu8 ? (((const unsigned char*)mask)[r] != 0)
                      : (((const int*)mask)[r] != 0);
        if (mv) {
            g_h[r * 128 + lane]      = xS[lane]      + c0;
            g_h[r * 128 + lane + 32] = xS[lane + 32] + c1;
            g_h[r * 128 + lane + 64] = xS[lane + 64] + c2;
            g_h[r * 128 + lane + 96] = xS[lane + 96] + c3;
        }
        __syncwarp();
    }
}
#define NODE_SMEM_FLOATS (24576 + 16384 + 128 + 128 + 8*196 + 8*132)
#define NODE_SMEM_BYTES (NODE_SMEM_FLOATS * 4)

// ---------------- launch ----------------
extern "C" void kernel_launch(void* const* d_in, const int* in_sizes, int n_in,
                              void* d_out, int out_size) {
    const float* h_in = (const float*)d_in[0];
    const int*   eA   = (const int*)d_in[1];
    const int*   eB   = (const int*)d_in[2];
    const void*  mA   = d_in[3];
    const void*  mB   = d_in[4];
    const float* Wi   = (const float*)d_in[5];
    const float* bi   = (const float*)d_in[6];
    const float* Wo   = (const float*)d_in[7];
    const float* bo   = (const float*)d_in[8];
    const float* ew1  = (const float*)d_in[9];
    const float* eb1  = (const float*)d_in[10];
    const float* ew2  = (const float*)d_in[11];
    const float* eb2  = (const float*)d_in[12];
    const float* nw1  = (const float*)d_in[13];
    const float* nb1  = (const float*)d_in[14];
    const float* nw2  = (const float*)d_in[15];
    const float* nb2  = (const float*)d_in[16];
    float* out = (float*)d_out;

    cudaFuncSetAttribute(edge_kernel, cudaFuncAttributeMaxDynamicSharedMemorySize,
                         EDGE_SMEM_BYTES);
    cudaFuncSetAttribute(node_kernel, cudaFuncAttributeMaxDynamicSharedMemorySize,
                         NODE_SMEM_BYTES);

    detect_mask_kernel<<<1, 256>>>((const unsigned int*)mA);
    embed_in_kernel<<<N_NODES / 16, 128>>>(h_in, Wi, bi);

    for (int i = 0; i < 4; i++) {
        const int* edges = (i % 2 == 0) ? eA : eB;
        const void* mask = (i % 2 == 0) ? mA : mB;
        float C = (i % 2 == 0) ? 1.0f : (2.0f / 64.0f);

        zero_agg_kernel<<<3125, 256>>>();
        edge_kernel<<<608, 256, EDGE_SMEM_BYTES>>>(
            edges, ew1 + i * 256 * 64, eb1 + i * 64,
            ew2 + i * 64 * 64, eb2 + i * 64, C, N_EDGES);
        node_kernel<<<608, 256, NODE_SMEM_BYTES>>>(
            mask, nw1 + i * 192 * 128, nb1 + i * 128,
            nw2 + i * 128 * 128, nb2 + i * 128);
    }

    embed_out_kernel<<<N_NODES / 16, 256>>>(Wo, bo, out);
}

// round 7
// speedup vs baseline: 2.9723x; 2.9723x over previous
#include <cuda_runtime.h>
#include <cuda_bf16.h>

typedef unsigned long long u64;

#define N_NODES 50000
#define N_EDGES 800000
#define HID 128
#define EH 64
#define FSTR 132            // floats per edge row in feat buffer (bank-spread)
#define EK_WARPS 16
#define CB 391              // ceil(800000 / 2048) compact blocks

// ---------------- scratch (no allocs allowed) ----------------
__device__ float g_h[N_NODES * HID];
__device__ float g_agg[N_NODES * EH];
__device__ int   g_mask_u8;
__device__ int   g_ne_c[2];                 // compacted edge counts
__device__ int   g_rows_c[2][N_EDGES];
__device__ int   g_cols_c[2][N_EDGES];

__device__ __forceinline__ float silu(float x) {
    return x / (1.0f + __expf(-x));
}
__device__ __forceinline__ u64 ffma2(u64 a, u64 b, u64 c) {
    u64 d;
    asm("fma.rn.f32x2 %0, %1, %2, %3;" : "=l"(d) : "l"(a), "l"(b), "l"(c));
    return d;
}
__device__ __forceinline__ float lo32(u64 a) { return __uint_as_float((unsigned)a); }
__device__ __forceinline__ float hi32(u64 a) { return __uint_as_float((unsigned)(a >> 32)); }
__device__ __forceinline__ u64 packf2(float lo, float hi) {
    return (u64)__float_as_uint(lo) | ((u64)__float_as_uint(hi) << 32);
}

// ---------------- mask dtype detection + counter reset ----------------
__global__ void detect_mask_kernel(const unsigned int* __restrict__ m) {
    if (threadIdx.x < 2) g_ne_c[threadIdx.x] = 0;
    int bad = 0;
    for (int i = threadIdx.x; i < N_NODES / 4; i += blockDim.x)
        if (m[i] > 1u) bad = 1;
    bad = __syncthreads_or(bad);
    if (threadIdx.x == 0) g_mask_u8 = bad;
}

// ---------------- edge compaction: keep edges with mask[row]==true ----------------
__global__ void __launch_bounds__(256)
compact_kernel(const int* __restrict__ edges, const void* __restrict__ mask, int li) {
    const int* rows = edges;
    const int* cols = edges + N_EDGES;
    __shared__ int s_wcnt[8];
    __shared__ int s_base;
    int tid = threadIdx.x, wid = tid >> 5, lane = tid & 31;
    int e0 = blockIdx.x * 2048;
    int mu8 = g_mask_u8;

    int rr[8], cc[8], off[8];
    unsigned vm = 0;
    int run = 0;
#pragma unroll
    for (int r = 0; r < 8; r++) {
        int e = e0 + r * 256 + tid;
        bool valid = false; int rv = 0, cv = 0;
        if (e < N_EDGES) {
            rv = rows[e]; cv = cols[e];
            valid = mu8 ? (((const unsigned char*)mask)[rv] != 0)
                        : (((const int*)mask)[rv] != 0);
        }
        rr[r] = rv; cc[r] = cv;
        if (valid) vm |= (1u << r);
        unsigned bal = __ballot_sync(0xffffffffu, valid);
        if (lane == 0) s_wcnt[wid] = __popc(bal);
        __syncthreads();
        int wbase = 0, tot = 0;
#pragma unroll
        for (int w = 0; w < 8; w++) { int c = s_wcnt[w]; if (w < wid) wbase += c; tot += c; }
        off[r] = run + wbase + __popc(bal & ((1u << lane) - 1u));
        run += tot;
        __syncthreads();
    }
    if (tid == 0) s_base = atomicAdd(&g_ne_c[li], run);
    __syncthreads();
    int base = s_base;
#pragma unroll
    for (int r = 0; r < 8; r++)
        if ((vm >> r) & 1u) {
            g_rows_c[li][base + off[r]] = rr[r];
            g_cols_c[li][base + off[r]] = cc[r];
        }
}

// ---------------- zero aggregation buffer ----------------
__global__ void zero_agg_kernel() {
    int i = blockIdx.x * blockDim.x + threadIdx.x;   // 800000 float4
    reinterpret_cast<float4*>(g_agg)[i] = make_float4(0.f, 0.f, 0.f, 0.f);
}

// ---------------- input embedding ----------------
__global__ void embed_in_kernel(const float* __restrict__ h_in,
                                const float* __restrict__ W,
                                const float* __restrict__ b) {
    __shared__ float Ws[64 * 128];
    __shared__ float xs[16][64];
    int tid = threadIdx.x;
    for (int i = tid; i < 64 * 128; i += 128) Ws[i] = W[i];
    int r0 = blockIdx.x * 16;
    for (int i = tid; i < 16 * 64; i += 128) {
        int rr = i >> 6, k = i & 63;
        xs[rr][k] = h_in[(r0 + rr) * 64 + k];
    }
    __syncthreads();
    int c = tid;
    float bc = b[c];
    for (int rr = 0; rr < 16; rr++) {
        float acc = bc;
#pragma unroll 8
        for (int k = 0; k < 64; k++) acc = fmaf(xs[rr][k], Ws[k * 128 + c], acc);
        g_h[(r0 + rr) * 128 + c] = acc;
    }
}

// ---------------- output embedding ----------------
__global__ void embed_out_kernel(const float* __restrict__ W,
                                 const float* __restrict__ b,
                                 float* __restrict__ out) {
    __shared__ float Ws[128 * 64];
    __shared__ float xs[16][128];
    int tid = threadIdx.x;
    for (int i = tid; i < 128 * 64; i += 256) Ws[i] = W[i];
    int r0 = blockIdx.x * 16;
    for (int i = tid; i < 16 * 128; i += 256) {
        int rr = i >> 7, k = i & 127;
        xs[rr][k] = g_h[(r0 + rr) * 128 + k];
    }
    __syncthreads();
    int c = tid & 63;
    int q = tid >> 6;
    float bc = b[c];
    for (int rr = q; rr < 16; rr += 4) {
        float acc = bc;
#pragma unroll 8
        for (int k = 0; k < 128; k++) acc = fmaf(xs[rr][k], Ws[k * 64 + c], acc);
        out[(r0 + rr) * 64 + c] = acc;
    }
}

// ---------------- edge kernel (FFMA2-packed) ----------------
// 16 warps/CTA; warp tile = 8 compacted edges. Lane (er=lane>>3, cg=lane&7)
// owns edges {er, er+4}, cols {2cg,2cg+1, 16+2cg,+1, 32+2cg,+1, 48+2cg,+1}.
// K is processed in even/odd pairs packed into 64-bit lanes (fma.rn.f32x2).
// Weights pre-packed in smem: Wp[kk*64 + c] = (W[2kk][c], W[2kk+1][c]).
// Features staged in two passes (h[row] then h[col]); buffer reused for m.
__global__ void __launch_bounds__(512, 1)
edge_kernel(int li,
            const float* __restrict__ W1, const float* __restrict__ b1,
            const float* __restrict__ W2, const float* __restrict__ b2,
            float C) {
    extern __shared__ char smraw[];
    u64* Wp1 = (u64*)smraw;                 // 8192 u64 = 64KB (all 256 k rows)
    u64* Wp2 = Wp1 + 8192;                  // 2048 u64 = 16KB
    float* b1s = (float*)(Wp2 + 2048);      // 64
    float* b2s = b1s + 64;                  // 64
    float* featAll = b2s + 64;              // 16 * 8 * FSTR floats
    __shared__ int idxAll[EK_WARPS][16];

    int tid = threadIdx.x;
    for (int i = tid; i < 8192; i += 512) {
        int kk = i >> 6, c = i & 63;
        Wp1[i] = packf2(W1[(2 * kk) * 64 + c], W1[(2 * kk + 1) * 64 + c]);
    }
    for (int i = tid; i < 2048; i += 512) {
        int kk = i >> 6, c = i & 63;
        Wp2[i] = packf2(W2[(2 * kk) * 64 + c], W2[(2 * kk + 1) * 64 + c]);
    }
    if (tid < 64) { b1s[tid] = b1[tid]; b2s[tid] = b2[tid]; }
    __syncthreads();

    int wid = tid >> 5, lane = tid & 31;
    int er = lane >> 3, cg = lane & 7;
    float* featS = featAll + wid * (8 * FSTR);
    int* idx = idxAll[wid];

    int colb[4] = {2 * cg, 16 + 2 * cg, 32 + 2 * cg, 48 + 2 * cg};
    float bb1[8], bb2[8];
#pragma unroll
    for (int q = 0; q < 4; q++) {
        bb1[2 * q] = b1s[colb[q]];     bb1[2 * q + 1] = b1s[colb[q] + 1];
        bb2[2 * q] = b2s[colb[q]];     bb2[2 * q + 1] = b2s[colb[q] + 1];
    }

    int nE = g_ne_c[li];
    const int* rows = g_rows_c[li];
    const int* cols = g_cols_c[li];
    int ngroups = (nE + 7) >> 3;
    int gw = blockIdx.x * EK_WARPS + wid;
    int nw = gridDim.x * EK_WARPS;

    const float* f0p = featS + er * FSTR;
    const float* f1p = featS + (er + 4) * FSTR;

    for (int g = gw; g < ngroups; g += nw) {
        int e0g = g * 8;
        if (lane < 16) {
            int e = e0g + (lane & 7);
            if (e >= nE) e = nE - 1;
            idx[lane] = (lane < 8) ? rows[e] : cols[e];
        }
        __syncwarp();

        u64 acc[16];
#pragma unroll
        for (int j = 0; j < 16; j++) acc[j] = 0ull;

        // ---- layer 1 (256 -> 64) in two K-passes of 128 ----
#pragma unroll
        for (int pass = 0; pass < 2; pass++) {
            for (int i = lane; i < 256; i += 32) {   // 8 edges x 32 float4
                int e = i >> 5, v = i & 31;
                int node = idx[e + (pass << 3)];
                *(float4*)(featS + e * FSTR + 4 * v) =
                    *(const float4*)(g_h + node * 128 + 4 * v);
            }
            __syncwarp();
            const u64* Wp = Wp1 + pass * 4096;
#pragma unroll 4
            for (int kk = 0; kk < 64; kk++) {
                u64 f0 = *(const u64*)(f0p + 2 * kk);
                u64 f1 = *(const u64*)(f1p + 2 * kk);
                const u64* wr = Wp + kk * 64;
                ulonglong2 w0 = *(const ulonglong2*)(wr + 2 * cg);
                ulonglong2 w1 = *(const ulonglong2*)(wr + 16 + 2 * cg);
                ulonglong2 w2 = *(const ulonglong2*)(wr + 32 + 2 * cg);
                ulonglong2 w3 = *(const ulonglong2*)(wr + 48 + 2 * cg);
                acc[0] = ffma2(f0, w0.x, acc[0]);   acc[1] = ffma2(f0, w0.y, acc[1]);
                acc[2] = ffma2(f0, w1.x, acc[2]);   acc[3] = ffma2(f0, w1.y, acc[3]);
                acc[4] = ffma2(f0, w2.x, acc[4]);   acc[5] = ffma2(f0, w2.y, acc[5]);
                acc[6] = ffma2(f0, w3.x, acc[6]);   acc[7] = ffma2(f0, w3.y, acc[7]);
                acc[8] = ffma2(f1, w0.x, acc[8]);   acc[9] = ffma2(f1, w0.y, acc[9]);
                acc[10] = ffma2(f1, w1.x, acc[10]); acc[11] = ffma2(f1, w1.y, acc[11]);
                acc[12] = ffma2(f1, w2.x, acc[12]); acc[13] = ffma2(f1, w2.y, acc[13]);
                acc[14] = ffma2(f1, w3.x, acc[14]); acc[15] = ffma2(f1, w3.y, acc[15]);
            }
            __syncwarp();
        }

        // ---- finalize layer1: m = silu(lo+hi+b1), stored back into featS ----
#pragma unroll
        for (int q = 0; q < 4; q++) {
            float2 m0, m1;
            m0.x = silu(lo32(acc[2*q])     + hi32(acc[2*q])     + bb1[2*q]);
            m0.y = silu(lo32(acc[2*q+1])   + hi32(acc[2*q+1])   + bb1[2*q+1]);
            m1.x = silu(lo32(acc[8+2*q])   + hi32(acc[8+2*q])   + bb1[2*q]);
            m1.y = silu(lo32(acc[8+2*q+1]) + hi32(acc[8+2*q+1]) + bb1[2*q+1]);
            *(float2*)(featS + er * FSTR + colb[q]) = m0;
            *(float2*)(featS + (er + 4) * FSTR + colb[q]) = m1;
        }
        __syncwarp();

        // ---- layer 2 (64 -> 64) ----
#pragma unroll
        for (int j = 0; j < 16; j++) acc[j] = 0ull;
#pragma unroll 4
        for (int kk = 0; kk < 32; kk++) {
            u64 f0 = *(const u64*)(f0p + 2 * kk);
            u64 f1 = *(const u64*)(f1p + 2 * kk);
            const u64* wr = Wp2 + kk * 64;
            ulonglong2 w0 = *(const ulonglong2*)(wr + 2 * cg);
            ulonglong2 w1 = *(const ulonglong2*)(wr + 16 + 2 * cg);
            ulonglong2 w2 = *(const ulonglong2*)(wr + 32 + 2 * cg);
            ulonglong2 w3 = *(const ulonglong2*)(wr + 48 + 2 * cg);
            acc[0] = ffma2(f0, w0.x, acc[0]);   acc[1] = ffma2(f0, w0.y, acc[1]);
            acc[2] = ffma2(f0, w1.x, acc[2]);   acc[3] = ffma2(f0, w1.y, acc[3]);
            acc[4] = ffma2(f0, w2.x, acc[4]);   acc[5] = ffma2(f0, w2.y, acc[5]);
            acc[6] = ffma2(f0, w3.x, acc[6]);   acc[7] = ffma2(f0, w3.y, acc[7]);
            acc[8] = ffma2(f1, w0.x, acc[8]);   acc[9] = ffma2(f1, w0.y, acc[9]);
            acc[10] = ffma2(f1, w1.x, acc[10]); acc[11] = ffma2(f1, w1.y, acc[11]);
            acc[12] = ffma2(f1, w2.x, acc[12]); acc[13] = ffma2(f1, w2.y, acc[13]);
            acc[14] = ffma2(f1, w3.x, acc[14]); acc[15] = ffma2(f1, w3.y, acc[15]);
        }

        // ---- scatter: agg[row] += silu(out) * C ----
        bool vA = (e0g + er) < nE;
        bool vB = (e0g + er + 4) < nE;
        int rA = idx[er], rB = idx[er + 4];
#pragma unroll
        for (int q = 0; q < 4; q++) {
            if (vA) {
                float* a = g_agg + rA * 64 + colb[q];
                atomicAdd(a,     silu(lo32(acc[2*q])   + hi32(acc[2*q])   + bb2[2*q])   * C);
                atomicAdd(a + 1, silu(lo32(acc[2*q+1]) + hi32(acc[2*q+1]) + bb2[2*q+1]) * C);
            }
            if (vB) {
                float* a = g_agg + rB * 64 + colb[q];
                atomicAdd(a,     silu(lo32(acc[8+2*q])   + hi32(acc[8+2*q])   + bb2[2*q])   * C);
                atomicAdd(a + 1, silu(lo32(acc[8+2*q+1]) + hi32(acc[8+2*q+1]) + bb2[2*q+1]) * C);
            }
        }
    }
}
#define EDGE_SMEM_BYTES (8192*8 + 2048*8 + 128*4 + EK_WARPS*8*FSTR*4)

// ---------------- node kernel (masked rows only) ----------------
__global__ void __launch_bounds__(512)
node_kernel(const void* __restrict__ mask,
            const float* __restrict__ W1, const float* __restrict__ b1,
            const float* __restrict__ W2, const float* __restrict__ b2) {
    extern __shared__ float sm[];
    float* W1s = sm;                   // 192*128 = 24576
    float* W2s = W1s + 24576;          // 128*128 = 16384
    float* b1s = W2s + 16384;          // 128
    float* b2s = b1s + 128;            // 128
    float* xAll = b2s + 128;           // 16 * 196
    float* mAll = xAll + 16 * 196;     // 16 * 132

    int tid = threadIdx.x;
    for (int i = tid; i < 24576; i += 512) W1s[i] = W1[i];
    for (int i = tid; i < 16384; i += 512) W2s[i] = W2[i];
    if (tid < 128) { b1s[tid] = b1[tid]; b2s[tid] = b2[tid]; }
    __syncthreads();

    int wid = tid >> 5, lane = tid & 31;
    float* xS = xAll + wid * 196;
    float* mS = mAll + wid * 132;
    int mu8 = g_mask_u8;

    int gw = blockIdx.x * 16 + wid;
    int nw = gridDim.x * 16;
    for (int r = gw; r < N_NODES; r += nw) {
        bool mv = mu8 ? (((const unsigned char*)mask)[r] != 0)
                      : (((const int*)mask)[r] != 0);
        if (!mv) continue;   // unmasked rows keep h unchanged -> skip all work

        for (int i = lane; i < 192; i += 32)
            xS[i] = (i < 128) ? g_h[r * 128 + i] : g_agg[r * 64 + (i - 128)];
        __syncwarp();

        float a0 = b1s[lane], a1 = b1s[lane + 32],
              a2 = b1s[lane + 64], a3 = b1s[lane + 96];
#pragma unroll 4
        for (int k = 0; k < 192; k++) {
            float f = xS[k];
            a0 = fmaf(f, W1s[k * 128 + lane],      a0);
            a1 = fmaf(f, W1s[k * 128 + lane + 32], a1);
            a2 = fmaf(f, W1s[k * 128 + lane + 64], a2);
            a3 = fmaf(f, W1s[k * 128 + lane + 96], a3);
        }
        mS[lane]      = silu(a0);
        mS[lane + 32] = silu(a1);
        mS[lane + 64] = silu(a2);
        mS[lane + 96] = silu(a3);
        __syncwarp();

        float c0 = b2s[lane], c1 = b2s[lane + 32],
              c2 = b2s[lane + 64], c3 = b2s[lane + 96];
#pragma unroll 4
        for (int k = 0; k < 128; k++) {
            float f = mS[k];
            c0 = fmaf(f, W2s[k * 128 + lane],      c0);
            c1 = fmaf(f, W2s[k * 128 + lane + 32], c1);
            c2 = fmaf(f, W2s[k * 128 + lane + 64], c2);
            c3 = fmaf(f, W2s[k * 128 + lane + 96], c3);
        }
        g_h[r * 128 + lane]      = xS[lane]      + c0;
        g_h[r * 128 + lane + 32] = xS[lane + 32] + c1;
        g_h[r * 128 + lane + 64] = xS[lane + 64] + c2;
        g_h[r * 128 + lane + 96] = xS[lane + 96] + c3;
        __syncwarp();
    }
}
#define NODE_SMEM_BYTES ((24576 + 16384 + 128 + 128 + 16*196 + 16*132) * 4)

// ---------------- launch ----------------
extern "C" void kernel_launch(void* const* d_in, const int* in_sizes, int n_in,
                              void* d_out, int out_size) {
    const float* h_in = (const float*)d_in[0];
    const int*   eA   = (const int*)d_in[1];
    const int*   eB   = (const int*)d_in[2];
    const void*  mA   = d_in[3];
    const void*  mB   = d_in[4];
    const float* Wi   = (const float*)d_in[5];
    const float* bi   = (const float*)d_in[6];
    const float* Wo   = (const float*)d_in[7];
    const float* bo   = (const float*)d_in[8];
    const float* ew1  = (const float*)d_in[9];
    const float* eb1  = (const float*)d_in[10];
    const float* ew2  = (const float*)d_in[11];
    const float* eb2  = (const float*)d_in[12];
    const float* nw1  = (const float*)d_in[13];
    const float* nb1  = (const float*)d_in[14];
    const float* nw2  = (const float*)d_in[15];
    const float* nb2  = (const float*)d_in[16];
    float* out = (float*)d_out;

    cudaFuncSetAttribute(edge_kernel, cudaFuncAttributeMaxDynamicSharedMemorySize,
                         EDGE_SMEM_BYTES);
    cudaFuncSetAttribute(node_kernel, cudaFuncAttributeMaxDynamicSharedMemorySize,
                         NODE_SMEM_BYTES);

    detect_mask_kernel<<<1, 256>>>((const unsigned int*)mA);
    compact_kernel<<<CB, 256>>>(eA, mA, 0);
    compact_kernel<<<CB, 256>>>(eB, mB, 1);
    embed_in_kernel<<<N_NODES / 16, 128>>>(h_in, Wi, bi);

    for (int i = 0; i < 4; i++) {
        int li = i % 2;
        const void* mask = (li == 0) ? mA : mB;
        float C = (li == 0) ? 1.0f : (2.0f / 64.0f);

        zero_agg_kernel<<<3125, 256>>>();
        edge_kernel<<<148, 512, EDGE_SMEM_BYTES>>>(
            li, ew1 + i * 256 * 64, eb1 + i * 64,
            ew2 + i * 64 * 64, eb2 + i * 64, C);
        node_kernel<<<148, 512, NODE_SMEM_BYTES>>>(
            mask, nw1 + i * 192 * 128, nb1 + i * 128,
            nw2 + i * 128 * 128, nb2 + i * 128);
    }

    embed_out_kernel<<<N_NODES / 16, 256>>>(Wo, bo, out);
}

// round 8
// speedup vs baseline: 3.8076x; 1.2810x over previous
#include <cuda_runtime.h>
#include <cuda_bf16.h>

typedef unsigned long long u64;

#define N_NODES 50000
#define N_EDGES 800000
#define HID 128
#define EH 64
#define FSTR 132            // floats per edge row in feat buffer (bank-spread)
#define EK_WARPS 16
#define CB 391              // ceil(800000 / 2048) edge compact blocks
#define NB 25               // ceil(50000 / 2048) node compact blocks

// ---------------- scratch (no allocs allowed) ----------------
__device__ float g_h[N_NODES * HID];
__device__ float g_agg[N_NODES * EH];
__device__ int   g_mask_u8;
__device__ int   g_ne_c[2];                 // compacted edge counts
__device__ int   g_rows_c[2][N_EDGES];
__device__ int   g_cols_c[2][N_EDGES];
__device__ int   g_nn_c[2];                 // compacted node counts
__device__ int   g_nodes_c[2][N_NODES];

__device__ __forceinline__ float silu(float x) {
    return x / (1.0f + __expf(-x));
}
__device__ __forceinline__ u64 ffma2(u64 a, u64 b, u64 c) {
    u64 d;
    asm("fma.rn.f32x2 %0, %1, %2, %3;" : "=l"(d) : "l"(a), "l"(b), "l"(c));
    return d;
}
__device__ __forceinline__ float lo32(u64 a) { return __uint_as_float((unsigned)a); }
__device__ __forceinline__ float hi32(u64 a) { return __uint_as_float((unsigned)(a >> 32)); }
__device__ __forceinline__ u64 packf2(float lo, float hi) {
    return (u64)__float_as_uint(lo) | ((u64)__float_as_uint(hi) << 32);
}
__device__ __forceinline__ void cp16(unsigned dst_smem, const void* src) {
    asm volatile("cp.async.cg.shared.global [%0], [%1], 16;"
                 :: "r"(dst_smem), "l"(src));
}
__device__ __forceinline__ void cp_commit() {
    asm volatile("cp.async.commit_group;");
}
template<int N> __device__ __forceinline__ void cp_wait() {
    asm volatile("cp.async.wait_group %0;" :: "n"(N));
}

// ---------------- mask dtype detection + counter reset ----------------
__global__ void detect_mask_kernel(const unsigned int* __restrict__ m) {
    if (threadIdx.x < 2) { g_ne_c[threadIdx.x] = 0; g_nn_c[threadIdx.x] = 0; }
    int bad = 0;
    for (int i = threadIdx.x; i < N_NODES / 4; i += blockDim.x)
        if (m[i] > 1u) bad = 1;
    bad = __syncthreads_or(bad);
    if (threadIdx.x == 0) g_mask_u8 = bad;
}

// ---------------- edge compaction: keep edges with mask[row]==true ----------------
__global__ void __launch_bounds__(256)
compact_kernel(const int* __restrict__ edges, const void* __restrict__ mask, int li) {
    const int* rows = edges;
    const int* cols = edges + N_EDGES;
    __shared__ int s_wcnt[8];
    __shared__ int s_base;
    int tid = threadIdx.x, wid = tid >> 5, lane = tid & 31;
    int e0 = blockIdx.x * 2048;
    int mu8 = g_mask_u8;

    int rr[8], cc[8], off[8];
    unsigned vm = 0;
    int run = 0;
#pragma unroll
    for (int r = 0; r < 8; r++) {
        int e = e0 + r * 256 + tid;
        bool valid = false; int rv = 0, cv = 0;
        if (e < N_EDGES) {
            rv = rows[e]; cv = cols[e];
            valid = mu8 ? (((const unsigned char*)mask)[rv] != 0)
                        : (((const int*)mask)[rv] != 0);
        }
        rr[r] = rv; cc[r] = cv;
        if (valid) vm |= (1u << r);
        unsigned bal = __ballot_sync(0xffffffffu, valid);
        if (lane == 0) s_wcnt[wid] = __popc(bal);
        __syncthreads();
        int wbase = 0, tot = 0;
#pragma unroll
        for (int w = 0; w < 8; w++) { int c = s_wcnt[w]; if (w < wid) wbase += c; tot += c; }
        off[r] = run + wbase + __popc(bal & ((1u << lane) - 1u));
        run += tot;
        __syncthreads();
    }
    if (tid == 0) s_base = atomicAdd(&g_ne_c[li], run);
    __syncthreads();
    int base = s_base;
#pragma unroll
    for (int r = 0; r < 8; r++)
        if ((vm >> r) & 1u) {
            g_rows_c[li][base + off[r]] = rr[r];
            g_cols_c[li][base + off[r]] = cc[r];
        }
}

// ---------------- node compaction: list of masked node ids ----------------
__global__ void __launch_bounds__(256)
compact_nodes_kernel(const void* __restrict__ mask, int li) {
    __shared__ int s_wcnt[8];
    __shared__ int s_base;
    int tid = threadIdx.x, wid = tid >> 5, lane = tid & 31;
    int n0 = blockIdx.x * 2048;
    int mu8 = g_mask_u8;

    int off[8];
    unsigned vm = 0;
    int run = 0;
#pragma unroll
    for (int r = 0; r < 8; r++) {
        int n = n0 + r * 256 + tid;
        bool valid = false;
        if (n < N_NODES)
            valid = mu8 ? (((const unsigned char*)mask)[n] != 0)
                        : (((const int*)mask)[n] != 0);
        if (valid) vm |= (1u << r);
        unsigned bal = __ballot_sync(0xffffffffu, valid);
        if (lane == 0) s_wcnt[wid] = __popc(bal);
        __syncthreads();
        int wbase = 0, tot = 0;
#pragma unroll
        for (int w = 0; w < 8; w++) { int c = s_wcnt[w]; if (w < wid) wbase += c; tot += c; }
        off[r] = run + wbase + __popc(bal & ((1u << lane) - 1u));
        run += tot;
        __syncthreads();
    }
    if (tid == 0) s_base = atomicAdd(&g_nn_c[li], run);
    __syncthreads();
    int base = s_base;
#pragma unroll
    for (int r = 0; r < 8; r++)
        if ((vm >> r) & 1u)
            g_nodes_c[li][base + off[r]] = n0 + r * 256 + tid;
}

// ---------------- zero aggregation buffer ----------------
__global__ void zero_agg_kernel() {
    int i = blockIdx.x * blockDim.x + threadIdx.x;   // 800000 float4
    reinterpret_cast<float4*>(g_agg)[i] = make_float4(0.f, 0.f, 0.f, 0.f);
}

// ---------------- input embedding (FFMA2, 4 rows/warp) ----------------
// g_h[r] = h_in[r] @ Wi + bi  ; Wi [64][128]
__global__ void __launch_bounds__(512, 1)
embed_in_kernel(const float* __restrict__ h_in,
                const float* __restrict__ W,
                const float* __restrict__ b) {
    extern __shared__ char smraw[];
    u64* Wp = (u64*)smraw;              // 32 kk * 128 cols
    float* bs = (float*)(Wp + 4096);    // 128
    float* xAll = bs + 128;             // 16 warps * 4 rows * 72

    int tid = threadIdx.x;
    for (int i = tid; i < 4096; i += 512) {
        int kk = i >> 7, c = i & 127;
        Wp[i] = packf2(W[(2 * kk) * 128 + c], W[(2 * kk + 1) * 128 + c]);
    }
    if (tid < 128) bs[tid] = b[tid];
    __syncthreads();

    int wid = tid >> 5, lane = tid & 31;
    float* xS = xAll + wid * 288;
    int c0 = 2 * lane, c1 = 64 + 2 * lane;
    float bb[4] = {bs[c0], bs[c0 + 1], bs[c1], bs[c1 + 1]};

    for (int t = blockIdx.x * 16 + wid; t < N_NODES / 4; t += gridDim.x * 16) {
        int r0 = 4 * t;
        for (int i = lane; i < 64; i += 32) {         // 4 rows x 16 float4
            int rr = i >> 4, v = i & 15;
            *(float4*)(xS + rr * 72 + 4 * v) =
                *(const float4*)(h_in + (r0 + rr) * 64 + 4 * v);
        }
        __syncwarp();
        u64 acc[16];
#pragma unroll
        for (int j = 0; j < 16; j++) acc[j] = 0ull;
#pragma unroll 4
        for (int kk = 0; kk < 32; kk++) {
            const u64* wr = Wp + kk * 128;
            ulonglong2 wA = *(const ulonglong2*)(wr + c0);
            ulonglong2 wB = *(const ulonglong2*)(wr + c1);
#pragma unroll
            for (int j = 0; j < 4; j++) {
                u64 f = *(const u64*)(xS + j * 72 + 2 * kk);
                acc[4 * j]     = ffma2(f, wA.x, acc[4 * j]);
                acc[4 * j + 1] = ffma2(f, wA.y, acc[4 * j + 1]);
                acc[4 * j + 2] = ffma2(f, wB.x, acc[4 * j + 2]);
                acc[4 * j + 3] = ffma2(f, wB.y, acc[4 * j + 3]);
            }
        }
#pragma unroll
        for (int j = 0; j < 4; j++) {
            float2 oA, oB;
            oA.x = lo32(acc[4 * j])     + hi32(acc[4 * j])     + bb[0];
            oA.y = lo32(acc[4 * j + 1]) + hi32(acc[4 * j + 1]) + bb[1];
            oB.x = lo32(acc[4 * j + 2]) + hi32(acc[4 * j + 2]) + bb[2];
            oB.y = lo32(acc[4 * j + 3]) + hi32(acc[4 * j + 3]) + bb[3];
            *(float2*)(g_h + (r0 + j) * 128 + c0) = oA;
            *(float2*)(g_h + (r0 + j) * 128 + c1) = oB;
        }
        __syncwarp();
    }
}
#define EMBI_SMEM (4096 * 8 + 128 * 4 + 16 * 288 * 4)

// ---------------- output embedding (FFMA2, 8 rows/warp) ----------------
// out[r] = g_h[r] @ Wo + bo ; Wo [128][64]
__global__ void __launch_bounds__(512, 1)
embed_out_kernel(const float* __restrict__ W,
                 const float* __restrict__ b,
                 float* __restrict__ out) {
    extern __shared__ char smraw[];
    u64* Wp = (u64*)smraw;              // 64 kk * 64 cols
    float* bs = (float*)(Wp + 4096);    // 64
    float* xAll = bs + 64;              // 16 warps * 8 rows * 136

    int tid = threadIdx.x;
    for (int i = tid; i < 4096; i += 512) {
        int kk = i >> 6, c = i & 63;
        Wp[i] = packf2(W[(2 * kk) * 64 + c], W[(2 * kk + 1) * 64 + c]);
    }
    if (tid < 64) bs[tid] = b[tid];
    __syncthreads();

    int wid = tid >> 5, lane = tid & 31;
    float* xS = xAll + wid * 1088;
    int c0 = 2 * lane;
    float bb0 = bs[c0], bb1 = bs[c0 + 1];

    for (int t = blockIdx.x * 16 + wid; t < N_NODES / 8; t += gridDim.x * 16) {
        int r0 = 8 * t;
        for (int i = lane; i < 256; i += 32) {        // 8 rows x 32 float4
            int rr = i >> 5, v = i & 31;
            *(float4*)(xS + rr * 136 + 4 * v) =
                *(const float4*)(g_h + (r0 + rr) * 128 + 4 * v);
        }
        __syncwarp();
        u64 acc[16];
#pragma unroll
        for (int j = 0; j < 16; j++) acc[j] = 0ull;
#pragma unroll 4
        for (int kk = 0; kk < 64; kk++) {
            ulonglong2 w = *(const ulonglong2*)(Wp + kk * 64 + c0);
#pragma unroll
            for (int j = 0; j < 8; j++) {
                u64 f = *(const u64*)(xS + j * 136 + 2 * kk);
                acc[2 * j]     = ffma2(f, w.x, acc[2 * j]);
                acc[2 * j + 1] = ffma2(f, w.y, acc[2 * j + 1]);
            }
        }
#pragma unroll
        for (int j = 0; j < 8; j++) {
            float2 o;
            o.x = lo32(acc[2 * j])     + hi32(acc[2 * j])     + bb0;
            o.y = lo32(acc[2 * j + 1]) + hi32(acc[2 * j + 1]) + bb1;
            *(float2*)(out + (r0 + j) * 64 + c0) = o;
        }
        __syncwarp();
    }
}
#define EMBO_SMEM (4096 * 8 + 64 * 4 + 16 * 1088 * 4)

// ---------------- edge MLP inner block (FFMA2) ----------------
template<int NKK>
__device__ __forceinline__ void mlp64(const float* f0p, const float* f1p,
                                      const u64* Wp, int cg, u64* acc) {
#pragma unroll 4
    for (int kk = 0; kk < NKK; kk++) {
        u64 f0 = *(const u64*)(f0p + 2 * kk);
        u64 f1 = *(const u64*)(f1p + 2 * kk);
        const u64* wr = Wp + kk * 64;
        ulonglong2 w0 = *(const ulonglong2*)(wr + 2 * cg);
        ulonglong2 w1 = *(const ulonglong2*)(wr + 16 + 2 * cg);
        ulonglong2 w2 = *(const ulonglong2*)(wr + 32 + 2 * cg);
        ulonglong2 w3 = *(const ulonglong2*)(wr + 48 + 2 * cg);
        acc[0] = ffma2(f0, w0.x, acc[0]);   acc[1] = ffma2(f0, w0.y, acc[1]);
        acc[2] = ffma2(f0, w1.x, acc[2]);   acc[3] = ffma2(f0, w1.y, acc[3]);
        acc[4] = ffma2(f0, w2.x, acc[4]);   acc[5] = ffma2(f0, w2.y, acc[5]);
        acc[6] = ffma2(f0, w3.x, acc[6]);   acc[7] = ffma2(f0, w3.y, acc[7]);
        acc[8] = ffma2(f1, w0.x, acc[8]);   acc[9] = ffma2(f1, w0.y, acc[9]);
        acc[10] = ffma2(f1, w1.x, acc[10]); acc[11] = ffma2(f1, w1.y, acc[11]);
        acc[12] = ffma2(f1, w2.x, acc[12]); acc[13] = ffma2(f1, w2.y, acc[13]);
        acc[14] = ffma2(f1, w3.x, acc[14]); acc[15] = ffma2(f1, w3.y, acc[15]);
    }
}

// ---------------- edge kernel (FFMA2 + cp.async double-buffered gather) ----------------
// 16 warps/CTA, 8 edges/warp-group. rows half -> bufA, cols half -> bufB.
// Pipeline: prefetch cols(g) during pass1 compute; rows(g+nw) during pass2.
__global__ void __launch_bounds__(512, 1)
edge_kernel(int li,
            const float* __restrict__ W1, const float* __restrict__ b1,
            const float* __restrict__ W2, const float* __restrict__ b2,
            float C) {
    extern __shared__ char smraw[];
    u64* Wp1 = (u64*)smraw;                 // 8192 u64
    u64* Wp2 = Wp1 + 8192;                  // 2048 u64
    float* b1s = (float*)(Wp2 + 2048);      // 64
    float* b2s = b1s + 64;                  // 64
    float* bufA_all = b2s + 64;             // 16 * 8 * FSTR
    float* bufB_all = bufA_all + EK_WARPS * 8 * FSTR;
    __shared__ int idxS[EK_WARPS][2][16];

    int tid = threadIdx.x;
    for (int i = tid; i < 8192; i += 512) {
        int kk = i >> 6, c = i & 63;
        Wp1[i] = packf2(W1[(2 * kk) * 64 + c], W1[(2 * kk + 1) * 64 + c]);
    }
    for (int i = tid; i < 2048; i += 512) {
        int kk = i >> 6, c = i & 63;
        Wp2[i] = packf2(W2[(2 * kk) * 64 + c], W2[(2 * kk + 1) * 64 + c]);
    }
    if (tid < 64) { b1s[tid] = b1[tid]; b2s[tid] = b2[tid]; }
    __syncthreads();

    int wid = tid >> 5, lane = tid & 31;
    int er = lane >> 3, cg = lane & 7;
    float* bufA = bufA_all + wid * (8 * FSTR);
    float* bufB = bufB_all + wid * (8 * FSTR);
    unsigned bufA_s = (unsigned)__cvta_generic_to_shared(bufA);
    unsigned bufB_s = (unsigned)__cvta_generic_to_shared(bufB);

    int colb[4] = {2 * cg, 16 + 2 * cg, 32 + 2 * cg, 48 + 2 * cg};
    float bb1[8], bb2[8];
#pragma unroll
    for (int q = 0; q < 4; q++) {
        bb1[2 * q] = b1s[colb[q]]; bb1[2 * q + 1] = b1s[colb[q] + 1];
        bb2[2 * q] = b2s[colb[q]]; bb2[2 * q + 1] = b2s[colb[q] + 1];
    }

    int nE = g_ne_c[li];
    const int* rows = g_rows_c[li];
    const int* cols = g_cols_c[li];
    int ngroups = (nE + 7) >> 3;
    int nw = gridDim.x * EK_WARPS;
    int g = blockIdx.x * EK_WARPS + wid;
    int cur = 0;

    const float* fA0 = bufA + er * FSTR;
    const float* fA1 = bufA + (er + 4) * FSTR;
    const float* fB0 = bufB + er * FSTR;
    const float* fB1 = bufB + (er + 4) * FSTR;

    if (g < ngroups) {
        if (lane < 16) {
            int e = g * 8 + (lane & 7);
            if (e >= nE) e = nE - 1;
            idxS[wid][0][lane] = (lane < 8) ? rows[e] : cols[e];
        }
        __syncwarp();
#pragma unroll
        for (int e = 0; e < 8; e++)
            cp16(bufA_s + (e * FSTR + 4 * lane) * 4,
                 g_h + (size_t)idxS[wid][0][e] * 128 + 4 * lane);
    }
    cp_commit();

    for (; g < ngroups; g += nw) {
        int* idx = idxS[wid][cur];
        // prefetch cols(current) -> bufB
#pragma unroll
        for (int e = 0; e < 8; e++)
            cp16(bufB_s + (e * FSTR + 4 * lane) * 4,
                 g_h + (size_t)idx[8 + e] * 128 + 4 * lane);
        cp_commit();
        cp_wait<1>(); __syncwarp();          // bufA (rows) ready

        u64 acc[16];
#pragma unroll
        for (int j = 0; j < 16; j++) acc[j] = 0ull;
        mlp64<64>(fA0, fA1, Wp1, cg, acc);   // layer1 pass1 (k 0..127)
        __syncwarp();                        // all lanes done reading bufA

        int gn = g + nw;
        int* idxn = idxS[wid][cur ^ 1];
        if (gn < ngroups) {
            if (lane < 16) {
                int e = gn * 8 + (lane & 7);
                if (e >= nE) e = nE - 1;
                idxn[lane] = (lane < 8) ? rows[e] : cols[e];
            }
            __syncwarp();
#pragma unroll
            for (int e = 0; e < 8; e++)
                cp16(bufA_s + (e * FSTR + 4 * lane) * 4,
                     g_h + (size_t)idxn[e] * 128 + 4 * lane);
        }
        cp_commit();
        cp_wait<1>(); __syncwarp();          // bufB (cols) ready

        mlp64<64>(fB0, fB1, Wp1 + 4096, cg, acc);  // layer1 pass2 (k 128..255)
        __syncwarp();

        // finalize layer1: m = silu(lo+hi+b1), stored into bufB
#pragma unroll
        for (int q = 0; q < 4; q++) {
            float2 m0, m1;
            m0.x = silu(lo32(acc[2*q])     + hi32(acc[2*q])     + bb1[2*q]);
            m0.y = silu(lo32(acc[2*q+1])   + hi32(acc[2*q+1])   + bb1[2*q+1]);
            m1.x = silu(lo32(acc[8+2*q])   + hi32(acc[8+2*q])   + bb1[2*q]);
            m1.y = silu(lo32(acc[8+2*q+1]) + hi32(acc[8+2*q+1]) + bb1[2*q+1]);
            *(float2*)(bufB + er * FSTR + colb[q]) = m0;
            *(float2*)(bufB + (er + 4) * FSTR + colb[q]) = m1;
        }
        __syncwarp();

        // layer2 (64 -> 64)
        u64 acc2[16];
#pragma unroll
        for (int j = 0; j < 16; j++) acc2[j] = 0ull;
        mlp64<32>(fB0, fB1, Wp2, cg, acc2);

        // scatter: agg[row] += silu(out) * C
        int e0g = g * 8;
        bool vA = (e0g + er) < nE;
        bool vB = (e0g + er + 4) < nE;
        int rA = idx[er], rB = idx[er + 4];
#pragma unroll
        for (int q = 0; q < 4; q++) {
            if (vA) {
                float* a = g_agg + rA * 64 + colb[q];
                atomicAdd(a,     silu(lo32(acc2[2*q])   + hi32(acc2[2*q])   + bb2[2*q])   * C);
                atomicAdd(a + 1, silu(lo32(acc2[2*q+1]) + hi32(acc2[2*q+1]) + bb2[2*q+1]) * C);
            }
            if (vB) {
                float* a = g_agg + rB * 64 + colb[q];
                atomicAdd(a,     silu(lo32(acc2[8+2*q])   + hi32(acc2[8+2*q])   + bb2[2*q])   * C);
                atomicAdd(a + 1, silu(lo32(acc2[8+2*q+1]) + hi32(acc2[8+2*q+1]) + bb2[2*q+1]) * C);
            }
        }
        __syncwarp();   // bufB reads done before next iteration's cols prefetch
        cur ^= 1;
    }
}
#define EDGE_SMEM_BYTES (8192*8 + 2048*8 + 128*4 + 2*EK_WARPS*8*FSTR*4)

// ---------------- node kernel (FFMA2, 4 compacted rows/warp) ----------------
__global__ void __launch_bounds__(512, 1)
node_kernel(int li,
            const float* __restrict__ W1, const float* __restrict__ b1,
            const float* __restrict__ W2, const float* __restrict__ b2) {
    extern __shared__ char smraw[];
    u64* Wp1 = (u64*)smraw;                 // 96 kk * 128 cols
    u64* Wp2 = Wp1 + 12288;                 // 64 kk * 128 cols
    float* b1s = (float*)(Wp2 + 8192);      // 128
    float* b2s = b1s + 128;                 // 128
    float* xAll = b2s + 128;                // 16 warps * 4 rows * 200

    int tid = threadIdx.x;
    for (int i = tid; i < 12288; i += 512) {
        int kk = i >> 7, c = i & 127;
        Wp1[i] = packf2(W1[(2 * kk) * 128 + c], W1[(2 * kk + 1) * 128 + c]);
    }
    for (int i = tid; i < 8192; i += 512) {
        int kk = i >> 7, c = i & 127;
        Wp2[i] = packf2(W2[(2 * kk) * 128 + c], W2[(2 * kk + 1) * 128 + c]);
    }
    if (tid < 128) { b1s[tid] = b1[tid]; b2s[tid] = b2[tid]; }
    __syncthreads();

    int wid = tid >> 5, lane = tid & 31;
    float* xS = xAll + wid * 800;
    int c0 = 2 * lane, c1 = 64 + 2 * lane;
    float bb1[4] = {b1s[c0], b1s[c0 + 1], b1s[c1], b1s[c1 + 1]};
    float bb2[4] = {b2s[c0], b2s[c0 + 1], b2s[c1], b2s[c1 + 1]};

    int nn = g_nn_c[li];
    const int* list = g_nodes_c[li];
    int ntiles = (nn + 3) >> 2;
    for (int t = blockIdx.x * 16 + wid; t < ntiles; t += gridDim.x * 16) {
        int rid[4]; bool rv[4];
#pragma unroll
        for (int j = 0; j < 4; j++) {
            int p = 4 * t + j;
            rv[j] = p < nn;
            rid[j] = list[rv[j] ? p : (nn - 1)];
        }
        // gather x = [h || agg]
#pragma unroll
        for (int j = 0; j < 4; j++) {
            for (int v = lane; v < 48; v += 32) {
                float4 val = (v < 32) ? *(const float4*)(g_h + (size_t)rid[j] * 128 + 4 * v)
                                      : *(const float4*)(g_agg + (size_t)rid[j] * 64 + 4 * (v - 32));
                *(float4*)(xS + j * 200 + 4 * v) = val;
            }
        }
        __syncwarp();

        u64 acc[16];
#pragma unroll
        for (int j = 0; j < 16; j++) acc[j] = 0ull;
#pragma unroll 2
        for (int kk = 0; kk < 96; kk++) {
            const u64* wr = Wp1 + kk * 128;
            ulonglong2 wA = *(const ulonglong2*)(wr + c0);
            ulonglong2 wB = *(const ulonglong2*)(wr + c1);
#pragma unroll
            for (int j = 0; j < 4; j++) {
                u64 f = *(const u64*)(xS + j * 200 + 2 * kk);
                acc[4 * j]     = ffma2(f, wA.x, acc[4 * j]);
                acc[4 * j + 1] = ffma2(f, wA.y, acc[4 * j + 1]);
                acc[4 * j + 2] = ffma2(f, wB.x, acc[4 * j + 2]);
                acc[4 * j + 3] = ffma2(f, wB.y, acc[4 * j + 3]);
            }
        }
        __syncwarp();   // all lanes done reading x before m overwrites

        float res[16];
#pragma unroll
        for (int j = 0; j < 4; j++) {
            res[4 * j]     = xS[j * 200 + c0];
            res[4 * j + 1] = xS[j * 200 + c0 + 1];
            res[4 * j + 2] = xS[j * 200 + c1];
            res[4 * j + 3] = xS[j * 200 + c1 + 1];
        }
#pragma unroll
        for (int j = 0; j < 4; j++) {
            float2 mA, mB;
            mA.x = silu(lo32(acc[4*j])     + hi32(acc[4*j])     + bb1[0]);
            mA.y = silu(lo32(acc[4*j+1])   + hi32(acc[4*j+1])   + bb1[1]);
            mB.x = silu(lo32(acc[4*j+2])   + hi32(acc[4*j+2])   + bb1[2]);
            mB.y = silu(lo32(acc[4*j+3])   + hi32(acc[4*j+3])   + bb1[3]);
            *(float2*)(xS + j * 200 + c0) = mA;
            *(float2*)(xS + j * 200 + c1) = mB;
        }
        __syncwarp();

#pragma unroll
        for (int j = 0; j < 16; j++) acc[j] = 0ull;
#pragma unroll 2
        for (int kk = 0; kk < 64; kk++) {
            const u64* wr = Wp2 + kk * 128;
            ulonglong2 wA = *(const ulonglong2*)(wr + c0);
            ulonglong2 wB = *(const ulonglong2*)(wr + c1);
#pragma unroll
            for (int j = 0; j < 4; j++) {
                u64 f = *(const u64*)(xS + j * 200 + 2 * kk);
                acc[4 * j]     = ffma2(f, wA.x, acc[4 * j]);
                acc[4 * j + 1] = ffma2(f, wA.y, acc[4 * j + 1]);
                acc[4 * j + 2] = ffma2(f, wB.x, acc[4 * j + 2]);
                acc[4 * j + 3] = ffma2(f, wB.y, acc[4 * j + 3]);
            }
        }
#pragma unroll
        for (int j = 0; j < 4; j++) {
            if (!rv[j]) continue;
            float2 oA, oB;
            oA.x = res[4*j]     + lo32(acc[4*j])     + hi32(acc[4*j])     + bb2[0];
            oA.y = res[4*j+1]   + lo32(acc[4*j+1])   + hi32(acc[4*j+1])   + bb2[1];
            oB.x = res[4*j+2]   + lo32(acc[4*j+2])   + hi32(acc[4*j+2])   + bb2[2];
            oB.y = res[4*j+3]   + lo32(acc[4*j+3])   + hi32(acc[4*j+3])   + bb2[3];
            *(float2*)(g_h + (size_t)rid[j] * 128 + c0) = oA;
            *(float2*)(g_h + (size_t)rid[j] * 128 + c1) = oB;
        }
        __syncwarp();
    }
}
#define NODE_SMEM_BYTES (12288*8 + 8192*8 + 256*4 + 16*800*4)

// ---------------- launch ----------------
extern "C" void kernel_launch(void* const* d_in, const int* in_sizes, int n_in,
                              void* d_out, int out_size) {
    const float* h_in = (const float*)d_in[0];
    const int*   eA   = (const int*)d_in[1];
    const int*   eB   = (const int*)d_in[2];
    const void*  mA   = d_in[3];
    const void*  mB   = d_in[4];
    const float* Wi   = (const float*)d_in[5];
    const float* bi   = (const float*)d_in[6];
    const float* Wo   = (const float*)d_in[7];
    const float* bo   = (const float*)d_in[8];
    const float* ew1  = (const float*)d_in[9];
    const float* eb1  = (const float*)d_in[10];
    const float* ew2  = (const float*)d_in[11];
    const float* eb2  = (const float*)d_in[12];
    const float* nw1  = (const float*)d_in[13];
    const float* nb1  = (const float*)d_in[14];
    const float* nw2  = (const float*)d_in[15];
    const float* nb2  = (const float*)d_in[16];
    float* out = (float*)d_out;

    cudaFuncSetAttribute(edge_kernel, cudaFuncAttributeMaxDynamicSharedMemorySize,
                         EDGE_SMEM_BYTES);
    cudaFuncSetAttribute(node_kernel, cudaFuncAttributeMaxDynamicSharedMemorySize,
                         NODE_SMEM_BYTES);
    cudaFuncSetAttribute(embed_in_kernel, cudaFuncAttributeMaxDynamicSharedMemorySize,
                         EMBI_SMEM);
    cudaFuncSetAttribute(embed_out_kernel, cudaFuncAttributeMaxDynamicSharedMemorySize,
                         EMBO_SMEM);

    detect_mask_kernel<<<1, 256>>>((const unsigned int*)mA);
    compact_kernel<<<CB, 256>>>(eA, mA, 0);
    compact_kernel<<<CB, 256>>>(eB, mB, 1);
    compact_nodes_kernel<<<NB, 256>>>(mA, 0);
    compact_nodes_kernel<<<NB, 256>>>(mB, 1);
    embed_in_kernel<<<148, 512, EMBI_SMEM>>>(h_in, Wi, bi);

    for (int i = 0; i < 4; i++) {
        int li = i % 2;
        float C = (li == 0) ? 1.0f : (2.0f / 64.0f);

        zero_agg_kernel<<<3125, 256>>>();
        edge_kernel<<<148, 512, EDGE_SMEM_BYTES>>>(
            li, ew1 + i * 256 * 64, eb1 + i * 64,
            ew2 + i * 64 * 64, eb2 + i * 64, C);
        node_kernel<<<148, 512, NODE_SMEM_BYTES>>>(
            li, nw1 + i * 192 * 128, nb1 + i * 128,
            nw2 + i * 128 * 128, nb2 + i * 128);
    }

    embed_out_kernel<<<148, 512, EMBO_SMEM>>>(Wo, bo, out);
}